// round 14
// baseline (speedup 1.0000x reference)
#include <cuda_runtime.h>
#include <float.h>

// ChamferDistance_755914244601: B=4, N=M=8192, 3D gaussian points.
// Grid-accelerated exact NN: counting-sort both sets into a 48^3 grid,
// then each query expands Chebyshev rings until best <= ((r-1)*h)^2.
// Exact same min as brute force, ~25x less pair work.

#define BB 4
#define NN 8192
#define MM 8192
#define GDIM 48
#define NC (GDIM * GDIM * GDIM)      // 110592 cells
#define DOM 5.2f                      // domain [-DOM, DOM]
#define HH (2.0f * DOM / GDIM)        // cell edge
#define INVH ((float)GDIM / (2.0f * DOM))
#define SCAN_T 1024
#define CPT (NC / SCAN_T)             // 108 cells per scan thread
#define TPB 256

// Scratch (device globals; no runtime allocation).
__device__ int   g_cnt1[BB * NC], g_start1[BB * NC], g_cur1[BB * NC];
__device__ int   g_cnt2[BB * NC], g_start2[BB * NC], g_cur2[BB * NC];
__device__ float4 g_sort1[BB * NN];   // (x,y,z, orig_idx bits), cell-sorted
__device__ float4 g_sort2[BB * MM];

static __device__ __forceinline__ int clampg(int v) {
    return v < 0 ? 0 : (v >= GDIM ? GDIM - 1 : v);
}
static __device__ __forceinline__ void cell_of(float x, float y, float z,
                                               int& cx, int& cy, int& cz) {
    cx = clampg((int)((x + DOM) * INVH));
    cy = clampg((int)((y + DOM) * INVH));
    cz = clampg((int)((z + DOM) * INVH));
}

__global__ void zero_kernel() {
    int i = blockIdx.x * blockDim.x + threadIdx.x;
    if (i < BB * NC) { g_cnt1[i] = 0; g_cnt2[i] = 0; }
}

__global__ void count_kernel(const float* __restrict__ pts, int npts,
                             int* __restrict__ cnt) {
    int i = blockIdx.x * blockDim.x + threadIdx.x;
    if (i >= BB * npts) return;
    int b = i / npts;
    const float* p = pts + (size_t)i * 3;
    int cx, cy, cz; cell_of(p[0], p[1], p[2], cx, cy, cz);
    atomicAdd(&cnt[b * NC + (cz * GDIM + cy) * GDIM + cx], 1);
}

// One block per batch: exclusive prefix over NC cells.
__global__ void __launch_bounds__(SCAN_T)
scan_kernel(const int* __restrict__ cnt, int* __restrict__ start,
            int* __restrict__ cur) {
    __shared__ int sm[SCAN_T];
    const int b = blockIdx.x, t = threadIdx.x;
    const int base = b * NC + t * CPT;
    int s = 0;
#pragma unroll 4
    for (int k = 0; k < CPT; k++) s += cnt[base + k];
    sm[t] = s;
    __syncthreads();
    for (int off = 1; off < SCAN_T; off <<= 1) {
        int v = (t >= off) ? sm[t - off] : 0;
        __syncthreads();
        sm[t] += v;
        __syncthreads();
    }
    int run = sm[t] - s;   // exclusive prefix of this thread's span
#pragma unroll 4
    for (int k = 0; k < CPT; k++) {
        start[base + k] = run;
        cur[base + k] = run;
        run += cnt[base + k];
    }
}

__global__ void scatter_kernel(const float* __restrict__ pts, int npts,
                               int* __restrict__ cur, float4* __restrict__ dst) {
    int i = blockIdx.x * blockDim.x + threadIdx.x;
    if (i >= BB * npts) return;
    int b = i / npts;
    int loc = i - b * npts;
    const float* p = pts + (size_t)i * 3;
    float x = p[0], y = p[1], z = p[2];
    int cx, cy, cz; cell_of(x, y, z, cx, cy, cz);
    int pos = atomicAdd(&cur[b * NC + (cz * GDIM + cy) * GDIM + cx], 1);
    dst[(size_t)b * npts + pos] = make_float4(x, y, z, __int_as_float(loc));
}

// Scan a contiguous run of cells [x0,x1] in row rowbase (cells contiguous in
// x have contiguous point ranges in the sorted array -> one linear scan).
static __device__ __forceinline__ void scan_row(
    const float4* __restrict__ dp, const int* __restrict__ st,
    const int* __restrict__ cn, int rowbase, int x0, int x1,
    float qx, float qy, float qz, float& best)
{
    if (x1 < 0 || x0 >= GDIM) return;
    x0 = x0 < 0 ? 0 : x0;
    x1 = x1 >= GDIM ? GDIM - 1 : x1;
    int c1 = rowbase + x1;
    int s = st[rowbase + x0];
    int e = st[c1] + cn[c1];
    for (int k = s; k < e; k++) {
        float4 p = dp[k];
        float dx = qx - p.x, dy = qy - p.y, dz = qz - p.z;
        float d = fmaf(dx, dx, fmaf(dy, dy, dz * dz));
        best = fminf(best, d);
    }
}

// Each thread: one query point (from its set's cell-sorted array, so warps
// are spatially coherent), expanding-ring exact NN against the other grid.
__global__ void query_kernel(const float4* __restrict__ qpts, int nq,
                             const float4* __restrict__ dpts, int nd,
                             const int* __restrict__ start,
                             const int* __restrict__ cnt,
                             float* __restrict__ outb)
{
    int i = blockIdx.x * blockDim.x + threadIdx.x;
    if (i >= BB * nq) return;
    int b = i / nq;
    float4 q = qpts[i];
    const float qx = q.x, qy = q.y, qz = q.z;
    const int qidx = __float_as_int(q.w);
    const float4* dp = dpts + (size_t)b * nd;
    const int* st = start + b * NC;
    const int* cn = cnt + b * NC;

    int cx, cy, cz; cell_of(qx, qy, qz, cx, cy, cz);
    float best = FLT_MAX;

    // ring 0
    scan_row(dp, st, cn, (cz * GDIM + cy) * GDIM, cx, cx, qx, qy, qz, best);

    // rings 1..: points in rings >= r lie at distance >= (r-1)*h
    for (int r = 1; r < GDIM; r++) {
        float bd = (float)(r - 1) * HH;
        if (best <= bd * bd) break;
        for (int dz = -r; dz <= r; dz++) {
            int zz = cz + dz;
            if ((unsigned)zz >= GDIM) continue;
            bool zface = (dz == -r) | (dz == r);
            for (int dy = -r; dy <= r; dy++) {
                int yy = cy + dy;
                if ((unsigned)yy >= GDIM) continue;
                int rowbase = (zz * GDIM + yy) * GDIM;
                if (zface | (dy == -r) | (dy == r)) {
                    scan_row(dp, st, cn, rowbase, cx - r, cx + r, qx, qy, qz, best);
                } else {
                    scan_row(dp, st, cn, rowbase, cx - r, cx - r, qx, qy, qz, best);
                    scan_row(dp, st, cn, rowbase, cx + r, cx + r, qx, qy, qz, best);
                }
            }
        }
    }
    outb[(size_t)b * nq + qidx] = best;   // each (b,qidx) written exactly once
}

extern "C" void kernel_launch(void* const* d_in, const int* in_sizes, int n_in,
                              void* d_out, int out_size)
{
    const float* xyz1 = (const float*)d_in[0];   // [B, N, 3]
    const float* xyz2 = (const float*)d_in[1];   // [B, M, 3]
    float* out = (float*)d_out;                  // [B*N + B*M]

    int* cnt1; int* start1; int* cur1; int* cnt2; int* start2; int* cur2;
    float4* s1; float4* s2;
    cudaGetSymbolAddress((void**)&cnt1,   g_cnt1);
    cudaGetSymbolAddress((void**)&start1, g_start1);
    cudaGetSymbolAddress((void**)&cur1,   g_cur1);
    cudaGetSymbolAddress((void**)&cnt2,   g_cnt2);
    cudaGetSymbolAddress((void**)&start2, g_start2);
    cudaGetSymbolAddress((void**)&cur2,   g_cur2);
    cudaGetSymbolAddress((void**)&s1,     g_sort1);
    cudaGetSymbolAddress((void**)&s2,     g_sort2);

    zero_kernel<<<(BB * NC + TPB - 1) / TPB, TPB>>>();

    count_kernel<<<(BB * NN + TPB - 1) / TPB, TPB>>>(xyz1, NN, cnt1);
    count_kernel<<<(BB * MM + TPB - 1) / TPB, TPB>>>(xyz2, MM, cnt2);

    scan_kernel<<<BB, SCAN_T>>>(cnt1, start1, cur1);
    scan_kernel<<<BB, SCAN_T>>>(cnt2, start2, cur2);

    scatter_kernel<<<(BB * NN + TPB - 1) / TPB, TPB>>>(xyz1, NN, cur1, s1);
    scatter_kernel<<<(BB * MM + TPB - 1) / TPB, TPB>>>(xyz2, MM, cur2, s2);

    // d1: queries = set1, data grid = set2.  d2: symmetric.
    query_kernel<<<(BB * NN + TPB - 1) / TPB, TPB>>>(s1, NN, s2, MM,
                                                     start2, cnt2, out);
    query_kernel<<<(BB * MM + TPB - 1) / TPB, TPB>>>(s2, MM, s1, NN,
                                                     start1, cnt1, out + BB * NN);
}

// round 15
// speedup vs baseline: 2.6576x; 2.6576x over previous
#include <cuda_runtime.h>
#include <float.h>

// ChamferDistance_755914244601: B=4, N=M=8192, 3D gaussian points.
// Grid-accelerated exact NN, warp-cooperative:
//  - counting-sort both sets into one global CSR (48^3 cells per set/batch)
//  - one warp per query: lane-strided coalesced scan of contiguous cell runs,
//    expanding Chebyshev rings with exact stop  best <= ((r-1)*h)^2
//  - row lower-bound pruning for tail queries.

#define BB 4
#define NN 8192
#define MM 8192
#define NQ1 (BB * NN)
#define NQ2 (BB * MM)
#define NQT (NQ1 + NQ2)
#define GDIM 48
#define NC (GDIM * GDIM * GDIM)
#define TC (BB * NC)            // cells per set
#define TC2 (2 * TC)            // 884736 total cells
#define DOM 5.2f
#define HH (2.0f * DOM / GDIM)  // 0.21667
#define HH2 (HH * HH)
#define INVH ((float)GDIM / (2.0f * DOM))
#define TPB 256
#define CPB 1024                // cells per scan block
#define NSB (TC2 / CPB)         // 864 scan blocks

// Scratch (device globals).
__device__ int    g_cnt[TC2];
__device__ int    g_st[TC2];
__device__ int    g_cur[TC2];
__device__ int    g_bsum[NSB];
__device__ int    g_bsex[NSB];
__device__ float4 g_sort[NQT];   // set1 sorted in [0,NQ1), set2 in [NQ1,NQT)

static __device__ __forceinline__ int clampg(int v) {
    return v < 0 ? 0 : (v >= GDIM ? GDIM - 1 : v);
}
static __device__ __forceinline__ int cell_of(float x, float y, float z) {
    int cx = clampg((int)((x + DOM) * INVH));
    int cy = clampg((int)((y + DOM) * INVH));
    int cz = clampg((int)((z + DOM) * INVH));
    return (cz * GDIM + cy) * GDIM + cx;
}

__global__ void zero_kernel() {
    int i = blockIdx.x * blockDim.x + threadIdx.x;
    if (i < TC2) g_cnt[i] = 0;
}

// Count both sets in one pass.
__global__ void count_kernel(const float* __restrict__ x1,
                             const float* __restrict__ x2) {
    int i = blockIdx.x * blockDim.x + threadIdx.x;
    if (i >= NQT) return;
    const float* p;
    int base;
    if (i < NQ1) { p = x1 + (size_t)i * 3; base = (i / NN) * NC; }
    else { int j = i - NQ1; p = x2 + (size_t)j * 3; base = TC + (j / MM) * NC; }
    atomicAdd(&g_cnt[base + cell_of(p[0], p[1], p[2])], 1);
}

// Stage 1: per-block sums (864 blocks x 256 thr x 4 cells).
__global__ void __launch_bounds__(TPB) bsum_kernel() {
    int base = blockIdx.x * CPB + threadIdx.x * 4;
    int4 c = *(const int4*)&g_cnt[base];
    int s = c.x + c.y + c.z + c.w;
#pragma unroll
    for (int o = 16; o; o >>= 1) s += __shfl_xor_sync(0xFFFFFFFFu, s, o);
    __shared__ int ws[8];
    if ((threadIdx.x & 31) == 0) ws[threadIdx.x >> 5] = s;
    __syncthreads();
    if (threadIdx.x == 0) {
        int t = 0;
#pragma unroll
        for (int i = 0; i < 8; i++) t += ws[i];
        g_bsum[blockIdx.x] = t;
    }
}

// Stage 2: scan the 864 block sums (single block).
__global__ void __launch_bounds__(1024) bscan_kernel() {
    __shared__ int sm[1024];
    int t = threadIdx.x;
    int v = (t < NSB) ? g_bsum[t] : 0;
    sm[t] = v;
    __syncthreads();
    for (int off = 1; off < 1024; off <<= 1) {
        int u = (t >= off) ? sm[t - off] : 0;
        __syncthreads();
        sm[t] += u;
        __syncthreads();
    }
    if (t < NSB) g_bsex[t] = sm[t] - v;   // exclusive
}

// Stage 3: local exclusive scan + offset -> st, cur.
__global__ void __launch_bounds__(TPB) lscan_kernel() {
    int base = blockIdx.x * CPB + threadIdx.x * 4;
    int4 c = *(const int4*)&g_cnt[base];
    int tsum = c.x + c.y + c.z + c.w;
    int lane = threadIdx.x & 31, wid = threadIdx.x >> 5;
    int x = tsum;
#pragma unroll
    for (int o = 1; o < 32; o <<= 1) {
        int v = __shfl_up_sync(0xFFFFFFFFu, x, o);
        if (lane >= o) x += v;
    }
    int wex = x - tsum;
    __shared__ int ws[8];
    if (lane == 31) ws[wid] = x;
    __syncthreads();
    if (threadIdx.x == 0) {
        int run = 0;
#pragma unroll
        for (int i = 0; i < 8; i++) { int t = ws[i]; ws[i] = run; run += t; }
    }
    __syncthreads();
    int off = g_bsex[blockIdx.x] + ws[wid] + wex;
    g_st[base] = off;     g_cur[base] = off;     off += c.x;
    g_st[base + 1] = off; g_cur[base + 1] = off; off += c.y;
    g_st[base + 2] = off; g_cur[base + 2] = off; off += c.z;
    g_st[base + 3] = off; g_cur[base + 3] = off;
}

// Scatter both sets into g_sort (cell-sorted, global positions).
__global__ void scatter_kernel(const float* __restrict__ x1,
                               const float* __restrict__ x2) {
    int i = blockIdx.x * blockDim.x + threadIdx.x;
    if (i >= NQT) return;
    const float* p;
    int base, loc;
    if (i < NQ1) { p = x1 + (size_t)i * 3; base = (i / NN) * NC; loc = i % NN; }
    else { int j = i - NQ1; p = x2 + (size_t)j * 3; base = TC + (j / MM) * NC; loc = j % MM; }
    float x = p[0], y = p[1], z = p[2];
    int pos = atomicAdd(&g_cur[base + cell_of(x, y, z)], 1);
    g_sort[pos] = make_float4(x, y, z, __int_as_float(loc));
}

// Lane-strided scan of contiguous cells [c0, c1] (same row -> contiguous run).
static __device__ __forceinline__ void scan_run(
    const int* __restrict__ st, const int* __restrict__ cn, int c0, int c1,
    float qx, float qy, float qz, int lane, float& best)
{
    int s = st[c0];
    int e = st[c1] + cn[c1];
    for (int k = s + lane; k < e; k += 32) {
        float4 p = g_sort[k];               // coalesced 16B per lane
        float dx = qx - p.x, dy = qy - p.y, dz = qz - p.z;
        best = fminf(best, fmaf(dx, dx, fmaf(dy, dy, dz * dz)));
    }
}

static __device__ __forceinline__ float warp_min(float v) {
    unsigned int u = __reduce_min_sync(0xFFFFFFFFu, __float_as_uint(v));
    return __uint_as_float(u);   // valid: all candidates >= 0
}

// One WARP per query. Queries = the sorted arrays themselves (warp-coherent).
__global__ void __launch_bounds__(TPB) query_kernel(float* __restrict__ out)
{
    const int gw = (blockIdx.x * blockDim.x + threadIdx.x) >> 5;
    const int lane = threadIdx.x & 31;

    float4 q = g_sort[gw];                  // broadcast load
    const float qx = q.x, qy = q.y, qz = q.z;
    const int qidx = __float_as_int(q.w);

    int stbase, oidx;
    if (gw < NQ1) {                          // query set1 -> data grid set2
        int b = gw / NN;
        stbase = TC + b * NC;
        oidx = b * NN + qidx;
    } else {                                 // query set2 -> data grid set1
        int b = (gw - NQ1) / MM;
        stbase = b * NC;
        oidx = NQ1 + b * MM + qidx;
    }
    const int* st = g_st + stbase;
    const int* cn = g_cnt + stbase;

    const int cx = clampg((int)((qx + DOM) * INVH));
    const int cy = clampg((int)((qy + DOM) * INVH));
    const int cz = clampg((int)((qz + DOM) * INVH));

    float best = FLT_MAX;

    // ring 0
    {
        int row = (cz * GDIM + cy) * GDIM;
        scan_run(st, cn, row + cx, row + cx, qx, qy, qz, lane, best);
    }

    // rings 1..: cells at Chebyshev ring >= r are >= (r-1)*h away.
    for (int r = 1; r <= GDIM; r++) {
        float bw = warp_min(best);
        float bd = (float)(r - 1) * HH;
        if (bw <= bd * bd) { best = bw; break; }
        best = bw;   // everyone carries the warp min (tightens pruning)

        const int zlo = cz - r < 0 ? 0 : cz - r;
        const int zhi = cz + r >= GDIM ? GDIM - 1 : cz + r;
        const int ylo = cy - r < 0 ? 0 : cy - r;
        const int yhi = cy + r >= GDIM ? GDIM - 1 : cy + r;
        const int xlo = cx - r < 0 ? 0 : cx - r;
        const int xhi = cx + r >= GDIM ? GDIM - 1 : cx + r;
        const float lbx = (float)((r - 1) * (r - 1)) * HH2;

        for (int zz = zlo; zz <= zhi; zz++) {
            int adz = zz - cz; adz = adz < 0 ? -adz : adz;
            const bool zface = (adz == r);
            const int dzb = adz > 0 ? adz - 1 : 0;
            const float lbz = (float)(dzb * dzb) * HH2;
            for (int yy = ylo; yy <= yhi; yy++) {
                int ady = yy - cy; ady = ady < 0 ? -ady : ady;
                const int dyb = ady > 0 ? ady - 1 : 0;
                const float lb = lbz + (float)(dyb * dyb) * HH2;
                if (lb >= best) continue;          // row can't beat best
                const int rowb = (zz * GDIM + yy) * GDIM;
                if (zface || ady == r) {
                    scan_run(st, cn, rowb + xlo, rowb + xhi, qx, qy, qz, lane, best);
                } else {
                    if (lb + lbx >= best) continue;  // end cells can't beat
                    if (cx - r >= 0)
                        scan_run(st, cn, rowb + cx - r, rowb + cx - r, qx, qy, qz, lane, best);
                    if (cx + r < GDIM)
                        scan_run(st, cn, rowb + cx + r, rowb + cx + r, qx, qy, qz, lane, best);
                }
            }
        }
    }

    float m = warp_min(best);
    if (lane == 0) out[oidx] = m;
}

extern "C" void kernel_launch(void* const* d_in, const int* in_sizes, int n_in,
                              void* d_out, int out_size)
{
    const float* xyz1 = (const float*)d_in[0];   // [B, N, 3]
    const float* xyz2 = (const float*)d_in[1];   // [B, M, 3]
    float* out = (float*)d_out;                  // [B*N + B*M]

    zero_kernel<<<(TC2 + TPB - 1) / TPB, TPB>>>();
    count_kernel<<<(NQT + TPB - 1) / TPB, TPB>>>(xyz1, xyz2);
    bsum_kernel<<<NSB, TPB>>>();
    bscan_kernel<<<1, 1024>>>();
    lscan_kernel<<<NSB, TPB>>>();
    scatter_kernel<<<(NQT + TPB - 1) / TPB, TPB>>>(xyz1, xyz2);
    query_kernel<<<(NQT * 32) / TPB, TPB>>>(out);   // one warp per query
}

// round 17
// speedup vs baseline: 11.2049x; 4.2161x over previous
#include <cuda_runtime.h>
#include <float.h>

// ChamferDistance_755914244601: B=4, N=M=8192, 3D gaussian points.
// Grid-accelerated exact NN, warp-per-query, NO ring walking:
//   scan the fixed 3^3 cell neighborhood (exact accept if best <= h^2),
//   else lane-strided brute-force over the full opposing set.
// Counting-sort CSR is global over {set1 batches, set2 batches} so batch
// point runs are contiguous and e = st[c+1] (sentinel at the end).

#define BB 4
#define NN 8192
#define MM 8192
#define NQ1 (BB * NN)
#define NQT (NQ1 + BB * MM)
#define GDIM 32
#define NC (GDIM * GDIM * GDIM)   // 32768
#define TC (BB * NC)              // 131072 cells per set
#define TC2 (2 * TC)              // 262144 total
#define DOM 5.2f
#define HH (2.0f * DOM / GDIM)    // 0.325
#define HH2 (HH * HH)             // 0.105625
#define INVH ((float)GDIM / (2.0f * DOM))
#define TPB 256
#define CPB 1024                  // cells per scan block
#define NSB (TC2 / CPB)           // 256 scan blocks

// Scratch (device globals).
__device__ int    g_cnt[TC2];
__device__ int    g_st[TC2 + 1];   // +1 sentinel = NQT
__device__ int    g_cur[TC2];
__device__ int    g_bsum[NSB];
__device__ int    g_bsex[NSB];
__device__ float4 g_sort[NQT];     // set1 batches then set2 batches, cell-sorted

static __device__ __forceinline__ int clampg(int v) {
    return v < 0 ? 0 : (v >= GDIM ? GDIM - 1 : v);
}
static __device__ __forceinline__ int cell_of(float x, float y, float z) {
    int cx = clampg((int)((x + DOM) * INVH));
    int cy = clampg((int)((y + DOM) * INVH));
    int cz = clampg((int)((z + DOM) * INVH));
    return (cz * GDIM + cy) * GDIM + cx;
}

__global__ void zero_kernel() {
    int i = blockIdx.x * blockDim.x + threadIdx.x;
    if (i < TC2) g_cnt[i] = 0;
    if (i == 0) g_st[TC2] = NQT;   // CSR sentinel
}

__global__ void count_kernel(const float* __restrict__ x1,
                             const float* __restrict__ x2) {
    int i = blockIdx.x * blockDim.x + threadIdx.x;
    if (i >= NQT) return;
    const float* p;
    int base;
    if (i < NQ1) { p = x1 + (size_t)i * 3; base = (i / NN) * NC; }
    else { int j = i - NQ1; p = x2 + (size_t)j * 3; base = TC + (j / MM) * NC; }
    atomicAdd(&g_cnt[base + cell_of(p[0], p[1], p[2])], 1);
}

__global__ void __launch_bounds__(TPB) bsum_kernel() {
    int base = blockIdx.x * CPB + threadIdx.x * 4;
    int4 c = *(const int4*)&g_cnt[base];
    int s = c.x + c.y + c.z + c.w;
#pragma unroll
    for (int o = 16; o; o >>= 1) s += __shfl_xor_sync(0xFFFFFFFFu, s, o);
    __shared__ int ws[8];
    if ((threadIdx.x & 31) == 0) ws[threadIdx.x >> 5] = s;
    __syncthreads();
    if (threadIdx.x == 0) {
        int t = 0;
#pragma unroll
        for (int i = 0; i < 8; i++) t += ws[i];
        g_bsum[blockIdx.x] = t;
    }
}

// Scan the 256 block sums (one block of 256 threads).
__global__ void __launch_bounds__(NSB) bscan_kernel() {
    __shared__ int sm[NSB];
    int t = threadIdx.x;
    int v = g_bsum[t];
    sm[t] = v;
    __syncthreads();
    for (int off = 1; off < NSB; off <<= 1) {
        int u = (t >= off) ? sm[t - off] : 0;
        __syncthreads();
        sm[t] += u;
        __syncthreads();
    }
    g_bsex[t] = sm[t] - v;   // exclusive
}

__global__ void __launch_bounds__(TPB) lscan_kernel() {
    int base = blockIdx.x * CPB + threadIdx.x * 4;
    int4 c = *(const int4*)&g_cnt[base];
    int tsum = c.x + c.y + c.z + c.w;
    int lane = threadIdx.x & 31, wid = threadIdx.x >> 5;
    int x = tsum;
#pragma unroll
    for (int o = 1; o < 32; o <<= 1) {
        int v = __shfl_up_sync(0xFFFFFFFFu, x, o);
        if (lane >= o) x += v;
    }
    int wex = x - tsum;
    __shared__ int ws[8];
    if (lane == 31) ws[wid] = x;
    __syncthreads();
    if (threadIdx.x == 0) {
        int run = 0;
#pragma unroll
        for (int i = 0; i < 8; i++) { int t = ws[i]; ws[i] = run; run += t; }
    }
    __syncthreads();
    int off = g_bsex[blockIdx.x] + ws[wid] + wex;
    g_st[base] = off;     g_cur[base] = off;     off += c.x;
    g_st[base + 1] = off; g_cur[base + 1] = off; off += c.y;
    g_st[base + 2] = off; g_cur[base + 2] = off; off += c.z;
    g_st[base + 3] = off; g_cur[base + 3] = off;
}

__global__ void scatter_kernel(const float* __restrict__ x1,
                               const float* __restrict__ x2) {
    int i = blockIdx.x * blockDim.x + threadIdx.x;
    if (i >= NQT) return;
    const float* p;
    int base, loc;
    if (i < NQ1) { p = x1 + (size_t)i * 3; base = (i / NN) * NC; loc = i % NN; }
    else { int j = i - NQ1; p = x2 + (size_t)j * 3; base = TC + (j / MM) * NC; loc = j % MM; }
    float x = p[0], y = p[1], z = p[2];
    int pos = atomicAdd(&g_cur[base + cell_of(x, y, z)], 1);
    g_sort[pos] = make_float4(x, y, z, __int_as_float(loc));
}

static __device__ __forceinline__ float warp_min(float v) {
    unsigned int u = __reduce_min_sync(0xFFFFFFFFu, __float_as_uint(v));
    return __uint_as_float(u);   // valid: distances >= 0
}

// One warp per query. 3^3 neighborhood scan, exact accept, else brute force.
__global__ void __launch_bounds__(TPB) query_kernel(float* __restrict__ out)
{
    const int gw = (blockIdx.x * blockDim.x + threadIdx.x) >> 5;
    const int lane = threadIdx.x & 31;

    float4 q = g_sort[gw];                  // queries = sorted arrays (coherent)
    const float qx = q.x, qy = q.y, qz = q.z;
    const int qidx = __float_as_int(q.w);

    int stbase, dbase, nd, oidx;
    if (gw < NQ1) {                          // set1 query -> set2 data
        int b = gw / NN;
        stbase = TC + b * NC;
        dbase  = NQ1 + b * MM;  nd = MM;
        oidx   = b * NN + qidx;
    } else {                                 // set2 query -> set1 data
        int b = (gw - NQ1) / MM;
        stbase = b * NC;
        dbase  = b * NN;        nd = NN;
        oidx   = NQ1 + b * MM + qidx;
    }

    const int cx = clampg((int)((qx + DOM) * INVH));
    const int cy = clampg((int)((qy + DOM) * INVH));
    const int cz = clampg((int)((qz + DOM) * INVH));
    const int x0 = cx - 1 < 0 ? 0 : cx - 1;
    const int x1 = cx + 1 >= GDIM ? GDIM - 1 : cx + 1;

    // All 9 row ranges up front: 18 independent loads in flight.
    int rs[9], re[9];
#pragma unroll
    for (int i = 0; i < 9; i++) {
        const int zz = cz + (i / 3) - 1;
        const int yy = cy + (i % 3) - 1;
        const bool ok = ((unsigned)zz < GDIM) && ((unsigned)yy < GDIM);
        const int rowb = stbase + (zz * GDIM + yy) * GDIM;
        rs[i] = ok ? g_st[rowb + x0] : 0;
        re[i] = ok ? g_st[rowb + x1 + 1] : 0;
    }

    float best = FLT_MAX;
#pragma unroll
    for (int i = 0; i < 9; i++) {
        for (int k = rs[i] + lane; k < re[i]; k += 32) {
            float4 p = g_sort[k];            // coalesced 16B/lane
            float dx = qx - p.x, dy = qy - p.y, dz = qz - p.z;
            best = fminf(best, fmaf(dx, dx, fmaf(dy, dy, dz * dz)));
        }
    }
    float m = warp_min(best);

    // Exact accept: any point outside the 3^3 box is > h away.
    if (m > HH2) {
        // rare fallback: flat brute force over the whole opposing batch
        best = m;
#pragma unroll 4
        for (int k = dbase + lane; k < dbase + nd; k += 32) {
            float4 p = g_sort[k];
            float dx = qx - p.x, dy = qy - p.y, dz = qz - p.z;
            best = fminf(best, fmaf(dx, dx, fmaf(dy, dy, dz * dz)));
        }
        m = warp_min(best);
    }

    if (lane == 0) out[oidx] = m;
}

extern "C" void kernel_launch(void* const* d_in, const int* in_sizes, int n_in,
                              void* d_out, int out_size)
{
    const float* xyz1 = (const float*)d_in[0];   // [B, N, 3]
    const float* xyz2 = (const float*)d_in[1];   // [B, M, 3]
    float* out = (float*)d_out;                  // [B*N + B*M]

    zero_kernel<<<(TC2 + TPB - 1) / TPB, TPB>>>();
    count_kernel<<<(NQT + TPB - 1) / TPB, TPB>>>(xyz1, xyz2);
    bsum_kernel<<<NSB, TPB>>>();
    bscan_kernel<<<1, NSB>>>();
    lscan_kernel<<<NSB, TPB>>>();
    scatter_kernel<<<(NQT + TPB - 1) / TPB, TPB>>>(xyz1, xyz2);
    query_kernel<<<(NQT * 32) / TPB, TPB>>>(out);   // one warp per query
}